// round 8
// baseline (speedup 1.0000x reference)
#include <cuda_runtime.h>
#include <cuda_fp16.h>
#include <math.h>
#include <stdint.h>

// Problem constants
#define BB   32
#define IDF_ 512
#define CDF_ 512
#define QQ   4096   // 64*64
#define LL   256

#define WC_ELEMS ((size_t)BB * IDF_ * QQ)

// ---------------------------------------------------------------------------
// Scratch (static device memory; no allocation at runtime)
// ---------------------------------------------------------------------------
__device__ float g_source [(size_t)BB * IDF_ * LL];   // [b][i][l]
__device__ float g_text   [(size_t)BB * IDF_ * LL];   // [b][i][l]
__device__ float g_img    [(size_t)BB * IDF_ * QQ];   // [b][o][q]
__device__ float g_attn   [(size_t)BB * QQ  * LL];    // [b][q][l]
__device__ float g_combine[(size_t)BB * QQ  * LL];    // [b][q][l]
__device__ float g_partial[BB * 16 * LL];
__device__ float g_rsums  [BB * LL];

// ---------------------------------------------------------------------------
// FP16 Markidis-split: v = hi + lo (each fp16). hh+hl+lh with fp32 accum
// gives ~fp32-equivalent results. split2 packs 2 elems into f16x2 words.
// ---------------------------------------------------------------------------
__device__ __forceinline__ void split2_f16(float v0, float v1,
                                           uint32_t& hi, uint32_t& lo) {
    __half2 h = __floats2half2_rn(v0, v1);
    float2 hf = __half22float2(h);
    __half2 l = __floats2half2_rn(v0 - hf.x, v1 - hf.y);
    hi = *(uint32_t*)&h;
    lo = *(uint32_t*)&l;
}

__device__ __forceinline__ void mma_f16(float* c, const uint32_t* a, const uint32_t* b) {
    asm volatile(
        "mma.sync.aligned.m16n8k16.row.col.f32.f16.f16.f32 "
        "{%0,%1,%2,%3}, {%4,%5,%6,%7}, {%8,%9}, {%0,%1,%2,%3};"
        : "+f"(c[0]), "+f"(c[1]), "+f"(c[2]), "+f"(c[3])
        : "r"(a[0]), "r"(a[1]), "r"(a[2]), "r"(a[3]), "r"(b[0]), "r"(b[1]));
}

__device__ __forceinline__ void cp_async16(uint32_t smem_dst, const void* gsrc) {
    asm volatile("cp.async.cg.shared.global [%0], [%1], 16;"
                 :: "r"(smem_dst), "l"(gsrc) : "memory");
}
#define CP_COMMIT() asm volatile("cp.async.commit_group;" ::: "memory")
#define CP_WAIT(n)  asm volatile("cp.async.wait_group %0;" :: "n"(n) : "memory")

#define LDSM4(r0, r1, r2, r3, addr) \
    asm volatile("ldmatrix.sync.aligned.m8n8.x4.shared.b16 {%0,%1,%2,%3}, [%4];" \
                 : "=r"(r0), "=r"(r1), "=r"(r2), "=r"(r3) : "r"(addr))

// ---------------------------------------------------------------------------
// Tensor-core GEMM, 3xFP16 split, split-once-per-block into fp16 h/l smem,
// ldmatrix fragment loads, cp.async 3-stage raw ring.
//   C[M,N] = op(A) * B (optional tanh).
//   TRANS_A=false: A [M,K] rm, raw staged [m][k] stride 20 w/ XOR-12 swizzle.
//   TRANS_A=true : A [K,M] rm, raw staged [k][m] stride 132.
//   B [K,N] rm, raw staged [k][n] stride 132.
// Convert stage: raw fp32 -> h/l fp16 buffers, layout [row][k] fp16, 32B rows,
// word column p stored at p ^ (row&4)  (conflict-free for STS.128 and LDSM).
// Block tile 128x128, K-chunk 16, 8 warps (2x4), warp tile 64x32.
// ---------------------------------------------------------------------------
template <bool TANH, bool TRANS_A>
__global__ __launch_bounds__(256, 2) void tgemm_kernel(
    const float* __restrict__ Ab, const float* __restrict__ Bb,
    float* __restrict__ Cb,
    int M, int N, int K,
    long long sA, long long sB, long long sC)
{
    constexpr int RA_WORDS = TRANS_A ? (16 * 132) : (128 * 20);
    constexpr int RB_WORDS = 16 * 132;
    constexpr int RA_BYTES = RA_WORDS * 4;
    constexpr int RB_BYTES = RB_WORDS * 4;
    constexpr int HL_STAGE = 16384;   // hA_h | hA_l | hB_h | hB_l, 4KB each

    extern __shared__ __align__(16) char smem[];
    char* rawA = smem;
    char* rawB = smem + 3 * RA_BYTES;
    char* hl   = rawB + 3 * RB_BYTES;
    const uint32_t rawA_u = (uint32_t)__cvta_generic_to_shared(rawA);
    const uint32_t rawB_u = (uint32_t)__cvta_generic_to_shared(rawB);
    const uint32_t hl_u   = (uint32_t)__cvta_generic_to_shared(hl);

    const float* A = Ab + (size_t)blockIdx.z * sA;
    const float* B = Bb + (size_t)blockIdx.z * sB;
    float*       C = Cb + (size_t)blockIdx.z * sC;

    const int tid  = threadIdx.x;
    const int lane = tid & 31;
    const int wid  = tid >> 5;
    const int m0   = blockIdx.y * 128;
    const int n0   = blockIdx.x * 128;
    const int wm   = (wid & 1) * 64;
    const int wn   = (wid >> 1) * 32;
    const int qr   = lane >> 2;
    const int tc   = lane & 3;

    float acc[4][4][4];
#pragma unroll
    for (int i = 0; i < 4; i++)
#pragma unroll
        for (int j = 0; j < 4; j++)
#pragma unroll
            for (int v = 0; v < 4; v++) acc[i][j][v] = 0.f;

    // ---- stage raw fp32 chunk k0 into ring slot s ----
    auto issue_chunk = [&](int k0, int s) {
#pragma unroll
        for (int j = 0; j < 2; j++) {
            int idx = tid + 256 * j;
            if (!TRANS_A) {
                int r = idx >> 2, c = (idx & 3) * 4;
                int dst = r * 20 + (c ^ ((r >> 3) & 12));
                cp_async16(rawA_u + s * RA_BYTES + 4 * dst,
                           A + (size_t)(m0 + r) * K + k0 + c);
            } else {
                int k = idx >> 5, m = (idx & 31) * 4;
                cp_async16(rawA_u + s * RA_BYTES + 4 * (k * 132 + m),
                           A + (size_t)(k0 + k) * M + m0 + m);
            }
            int k = idx >> 5, n = (idx & 31) * 4;
            cp_async16(rawB_u + s * RB_BYTES + 4 * (k * 132 + n),
                       B + (size_t)(k0 + k) * N + n0 + n);
        }
        CP_COMMIT();
    };

    // ---- convert raw chunk c -> fp16 h/l buffers (parity c&1) ----
    const int cr  = tid >> 1;     // row (m or n), 0..127
    const int ckh = tid & 1;      // k half
    auto convert = [&](int c) {
        const float* ra = (const float*)(rawA + (c % 3) * RA_BYTES);
        const float* rb = (const float*)(rawB + (c % 3) * RB_BYTES);
        uint32_t* hAh = (uint32_t*)(hl + (c & 1) * HL_STAGE);
        uint32_t* hAl = hAh + 1024;
        uint32_t* hBh = hAh + 2048;
        uint32_t* hBl = hAh + 3072;
        const int woff = cr * 8 + ((4 * ckh) ^ (cr & 4));
        uint4 H, L;
        // A
        if (!TRANS_A) {
            const float* row = ra + cr * 20;
            int key = (cr >> 3) & 12;
            float4 v0 = *(const float4*)(row + ((8 * ckh)     ^ key));
            float4 v1 = *(const float4*)(row + ((8 * ckh + 4) ^ key));
            split2_f16(v0.x, v0.y, H.x, L.x);
            split2_f16(v0.z, v0.w, H.y, L.y);
            split2_f16(v1.x, v1.y, H.z, L.z);
            split2_f16(v1.z, v1.w, H.w, L.w);
        } else {
            const float* col = ra + cr;
            const int kb = 8 * ckh;
#pragma unroll
            for (int j = 0; j < 4; j++) {
                float a = col[(kb + 2 * j)     * 132];
                float b = col[(kb + 2 * j + 1) * 132];
                split2_f16(a, b, (&H.x)[j], (&L.x)[j]);
            }
        }
        *(uint4*)(hAh + woff) = H;
        *(uint4*)(hAl + woff) = L;
        // B : [k][n] raw -> [n][k] h/l (transpose at convert)
        {
            const float* col = rb + cr;
            const int kb = 8 * ckh;
#pragma unroll
            for (int j = 0; j < 4; j++) {
                float a = col[(kb + 2 * j)     * 132];
                float b = col[(kb + 2 * j + 1) * 132];
                split2_f16(a, b, (&H.x)[j], (&L.x)[j]);
            }
            *(uint4*)(hBh + woff) = H;
            *(uint4*)(hBl + woff) = L;
        }
    };

    // ---- MMA over fp16 h/l chunk (parity c&1) ----
    const int rl  = lane & 15;
    const int khl = lane >> 4;
    auto mma_chunk = [&](int c) {
        const uint32_t hAh_u = hl_u + (c & 1) * HL_STAGE;
        const uint32_t hAl_u = hAh_u + 4096;
        const uint32_t hBh_u = hAh_u + 8192;
        const uint32_t hBl_u = hAh_u + 12288;
        uint32_t bh[4][2], bl[4][2];
#pragma unroll
        for (int nip = 0; nip < 2; nip++) {
            int n = wn + 16 * nip + rl;
            uint32_t off = n * 32 + (((khl * 4) ^ (n & 4)) << 2);
            uint32_t t0, t1, t2, t3;
            LDSM4(t0, t1, t2, t3, hBh_u + off);
            bh[2 * nip][0] = t0; bh[2 * nip + 1][0] = t1;
            bh[2 * nip][1] = t2; bh[2 * nip + 1][1] = t3;
            LDSM4(t0, t1, t2, t3, hBl_u + off);
            bl[2 * nip][0] = t0; bl[2 * nip + 1][0] = t1;
            bl[2 * nip][1] = t2; bl[2 * nip + 1][1] = t3;
        }
#pragma unroll
        for (int mi = 0; mi < 4; mi++) {
            int r = wm + 16 * mi + rl;
            uint32_t off = r * 32 + (((khl * 4) ^ (r & 4)) << 2);
            uint32_t ah[4], al[4];
            LDSM4(ah[0], ah[1], ah[2], ah[3], hAh_u + off);
            LDSM4(al[0], al[1], al[2], al[3], hAl_u + off);
#pragma unroll
            for (int ni = 0; ni < 4; ni++) {
                mma_f16(acc[mi][ni], ah, bh[ni]);
                mma_f16(acc[mi][ni], ah, bl[ni]);
                mma_f16(acc[mi][ni], al, bh[ni]);
            }
        }
    };

    const int nchunk = K >> 4;
    issue_chunk(0, 0);
    issue_chunk(16, 1);
    CP_WAIT(1);
    __syncthreads();
    convert(0);

    for (int c = 0; c < nchunk; c++) {
        if (c + 2 < nchunk) { issue_chunk((c + 2) << 4, (c + 2) % 3); CP_WAIT(1); }
        else                { CP_WAIT(0); }
        __syncthreads();
        if (c + 1 < nchunk) convert(c + 1);
        mma_chunk(c);
    }

    // ---- epilogue (C fragment layout as m16n8k8) ----
#pragma unroll
    for (int mi = 0; mi < 4; mi++) {
#pragma unroll
        for (int ni = 0; ni < 4; ni++) {
            int r0  = m0 + wm + 16 * mi + qr;
            int col = n0 + wn + 8 * ni + 2 * tc;
            float c0 = acc[mi][ni][0], c1 = acc[mi][ni][1];
            float c2 = acc[mi][ni][2], c3 = acc[mi][ni][3];
            if (TANH) { c0 = tanhf(c0); c1 = tanhf(c1); c2 = tanhf(c2); c3 = tanhf(c3); }
            *(float2*)(C + (size_t)r0 * N + col)       = make_float2(c0, c1);
            *(float2*)(C + (size_t)(r0 + 8) * N + col) = make_float2(c2, c3);
        }
    }
}

// dynamic smem sizes per instantiation
#define SMEM_NN (3 * 128 * 20 * 4 + 3 * 16 * 132 * 4 + 2 * 16384)  // 88832
#define SMEM_TN (3 * 16 * 132 * 4 + 3 * 16 * 132 * 4 + 2 * 16384)  // 83456

// ---------------------------------------------------------------------------
// Small FFMA SGEMM (two tiny ctx GEMMs; exact fp32).
// ---------------------------------------------------------------------------
template <bool TANH>
__global__ __launch_bounds__(256) void sgemm_kernel(
    const float* __restrict__ Ab, const float* __restrict__ Bb,
    float* __restrict__ Cb,
    int M, int N, int K,
    long long sA, long long sB, long long sC)
{
    const float* A = Ab + (size_t)blockIdx.z * sA;
    const float* B = Bb + (size_t)blockIdx.z * sB;
    float*       C = Cb + (size_t)blockIdx.z * sC;

    __shared__ float As[8][128];
    __shared__ float Bs[8][128];

    const int tid = threadIdx.x;
    const int m0  = blockIdx.y * 128;
    const int n0  = blockIdx.x * 128;
    const int tx = tid & 15;
    const int ty = tid >> 4;
    const int brow = tid >> 5;
    const int bcol = (tid & 31) * 4;
    const int arow = tid >> 1;
    const int acol = (tid & 1) * 4;

    float acc[8][8];
#pragma unroll
    for (int i = 0; i < 8; i++)
#pragma unroll
        for (int j = 0; j < 8; j++) acc[i][j] = 0.f;

    for (int k0 = 0; k0 < K; k0 += 8) {
        float4 a = *(const float4*)(A + (size_t)(m0 + arow) * K + k0 + acol);
        As[acol + 0][arow] = a.x;
        As[acol + 1][arow] = a.y;
        As[acol + 2][arow] = a.z;
        As[acol + 3][arow] = a.w;
        float4 b = *(const float4*)(B + (size_t)(k0 + brow) * N + n0 + bcol);
        *(float4*)&Bs[brow][bcol] = b;
        __syncthreads();
#pragma unroll
        for (int kk = 0; kk < 8; kk++) {
            float ar[8], br[8];
            *(float4*)&ar[0] = *(float4*)&As[kk][ty * 8];
            *(float4*)&ar[4] = *(float4*)&As[kk][ty * 8 + 4];
            *(float4*)&br[0] = *(float4*)&Bs[kk][tx * 8];
            *(float4*)&br[4] = *(float4*)&Bs[kk][tx * 8 + 4];
#pragma unroll
            for (int i = 0; i < 8; i++)
#pragma unroll
                for (int j = 0; j < 8; j++) acc[i][j] += ar[i] * br[j];
        }
        __syncthreads();
    }
#pragma unroll
    for (int i = 0; i < 8; i++) {
        size_t base = (size_t)(m0 + ty * 8 + i) * N + n0 + tx * 8;
        float4 v0, v1;
        if (TANH) {
            v0.x = tanhf(acc[i][0]); v0.y = tanhf(acc[i][1]);
            v0.z = tanhf(acc[i][2]); v0.w = tanhf(acc[i][3]);
            v1.x = tanhf(acc[i][4]); v1.y = tanhf(acc[i][5]);
            v1.z = tanhf(acc[i][6]); v1.w = tanhf(acc[i][7]);
        } else {
            v0.x = acc[i][0]; v0.y = acc[i][1]; v0.z = acc[i][2]; v0.w = acc[i][3];
            v1.x = acc[i][4]; v1.y = acc[i][5]; v1.z = acc[i][6]; v1.w = acc[i][7];
        }
        *(float4*)(C + base)     = v0;
        *(float4*)(C + base + 4) = v1;
    }
}

// ---------------------------------------------------------------------------
// Softmax over L=256 (in place), one block per row.
// ---------------------------------------------------------------------------
__global__ __launch_bounds__(256) void softmax_rows256(float* __restrict__ data)
{
    const size_t row = blockIdx.x;
    const int t = threadIdx.x;
    float v = data[row * LL + t];

    __shared__ float red[8];
    float m = v;
#pragma unroll
    for (int o = 16; o; o >>= 1) m = fmaxf(m, __shfl_xor_sync(0xffffffffu, m, o));
    if ((t & 31) == 0) red[t >> 5] = m;
    __syncthreads();
    if (t < 8) {
        float x = red[t];
#pragma unroll
        for (int o = 4; o; o >>= 1) x = fmaxf(x, __shfl_xor_sync(0xffu, x, o));
        if (t == 0) red[0] = x;
    }
    __syncthreads();
    m = red[0];
    float e = expf(v - m);
    __syncthreads();
    float s = e;
#pragma unroll
    for (int o = 16; o; o >>= 1) s += __shfl_xor_sync(0xffffffffu, s, o);
    if ((t & 31) == 0) red[t >> 5] = s;
    __syncthreads();
    if (t < 8) {
        float x = red[t];
#pragma unroll
        for (int o = 4; o; o >>= 1) x += __shfl_xor_sync(0xffu, x, o);
        if (t == 0) red[0] = x;
    }
    __syncthreads();
    data[row * LL + t] = e / red[0];
}

// ---------------------------------------------------------------------------
// Second softmax (over Q): partial sum-exp, reduce to reciprocal.
// ---------------------------------------------------------------------------
__global__ __launch_bounds__(256) void sumexp_partial_kernel()
{
    const int b = blockIdx.x;
    const int chunk = blockIdx.y;
    const int l = threadIdx.x;
    const size_t base = ((size_t)b * QQ + (size_t)chunk * 256) * LL + l;
    float s = 0.f;
#pragma unroll 8
    for (int q = 0; q < 256; q++) s += expf(g_attn[base + (size_t)q * LL]);
    g_partial[(b * 16 + chunk) * LL + l] = s;
}

__global__ __launch_bounds__(256) void sumexp_reduce_kernel()
{
    const int b = blockIdx.x;
    const int l = threadIdx.x;
    float s = 0.f;
#pragma unroll
    for (int c = 0; c < 16; c++) s += g_partial[(b * 16 + c) * LL + l];
    g_rsums[b * LL + l] = 1.0f / s;
}

// ---------------------------------------------------------------------------
// Finalize: exp * (1/sum) * combine, transposed into attn_map [b][l][q].
// ---------------------------------------------------------------------------
__global__ __launch_bounds__(256) void finalize_kernel(float* __restrict__ out_am)
{
    const int b  = blockIdx.y;
    const int q0 = blockIdx.x * 32;
    const int tx = threadIdx.x;
    const int ty = threadIdx.y;

    __shared__ float tile[32][33];

    for (int l0 = 0; l0 < LL; l0 += 32) {
        const float rs_col = g_rsums[b * LL + l0 + tx];
#pragma unroll
        for (int r = 0; r < 4; r++) {
            const int q = q0 + ty + 8 * r;
            const size_t idx = ((size_t)b * QQ + q) * LL + l0 + tx;
            tile[ty + 8 * r][tx] = expf(g_attn[idx]) * rs_col * g_combine[idx];
        }
        __syncthreads();
#pragma unroll
        for (int r = 0; r < 4; r++) {
            const int l = l0 + ty + 8 * r;
            out_am[((size_t)b * LL + l) * QQ + q0 + tx] = tile[tx][ty + 8 * r];
        }
        __syncthreads();
    }
}

// ---------------------------------------------------------------------------
// Launcher
// ---------------------------------------------------------------------------
extern "C" void kernel_launch(void* const* d_in, const int* in_sizes, int n_in,
                              void* d_out, int out_size)
{
    const float* x         = (const float*)d_in[0];
    const float* context   = (const float*)d_in[1];
    const float* w_context = (const float*)d_in[2];
    const float* w_img     = (const float*)d_in[3];
    const float* w_text    = (const float*)d_in[4];

    float* out_wc = (float*)d_out;
    float* out_am = out_wc + WC_ELEMS;

    float *p_source, *p_text, *p_img, *p_attn, *p_combine;
    cudaGetSymbolAddress((void**)&p_source,  g_source);
    cudaGetSymbolAddress((void**)&p_text,    g_text);
    cudaGetSymbolAddress((void**)&p_img,     g_img);
    cudaGetSymbolAddress((void**)&p_attn,    g_attn);
    cudaGetSymbolAddress((void**)&p_combine, g_combine);

    cudaFuncSetAttribute(tgemm_kernel<true,  false>,
        cudaFuncAttributeMaxDynamicSharedMemorySize, SMEM_NN);
    cudaFuncSetAttribute(tgemm_kernel<false, false>,
        cudaFuncAttributeMaxDynamicSharedMemorySize, SMEM_NN);
    cudaFuncSetAttribute(tgemm_kernel<true,  true>,
        cudaFuncAttributeMaxDynamicSharedMemorySize, SMEM_TN);
    cudaFuncSetAttribute(tgemm_kernel<false, true>,
        cudaFuncAttributeMaxDynamicSharedMemorySize, SMEM_TN);

    const long long sCTX = (long long)CDF_ * LL;
    const long long sSL  = (long long)IDF_ * LL;
    const long long sIQ  = (long long)IDF_ * QQ;
    const long long sQL  = (long long)QQ * LL;

    // 1) source = W_ctx @ ctx (exact fp32, feeds attn logits)
    sgemm_kernel<false><<<dim3(2, 4, BB), 256>>>(
        w_context, context, p_source, IDF_, LL, CDF_, 0, sCTX, sSL);
    // 2) text = tanh(W_text @ ctx)
    sgemm_kernel<true><<<dim3(2, 4, BB), 256>>>(
        w_text, context, p_text, IDF_, LL, CDF_, 0, sCTX, sSL);
    // 3) img = tanh(W_img @ x) — 3xFP16, split-once + ldmatrix
    tgemm_kernel<true, false><<<dim3(32, 4, BB), 256, SMEM_NN>>>(
        w_img, x, p_img, IDF_, QQ, IDF_, 0, sIQ, sIQ);
    // 4) attn = x^T @ source
    tgemm_kernel<false, true><<<dim3(2, 32, BB), 256, SMEM_TN>>>(
        x, p_source, p_attn, QQ, LL, IDF_, sIQ, sSL, sQL);
    // 5) combine = tanh(img^T @ text)
    tgemm_kernel<true, true><<<dim3(2, 32, BB), 256, SMEM_TN>>>(
        p_img, p_text, p_combine, QQ, LL, IDF_, sIQ, sSL, sQL);
    // 6) softmax over L
    softmax_rows256<<<BB * QQ, 256>>>(p_attn);
    // 7) second softmax over Q
    sumexp_partial_kernel<<<dim3(BB, 16), 256>>>();
    sumexp_reduce_kernel<<<BB, 256>>>();
    // 8) finalize into attn_map [b][l][q]
    finalize_kernel<<<dim3(QQ / 32, BB), dim3(32, 8)>>>(out_am);
    // 9) weighted_context = source @ attn_map
    tgemm_kernel<false, false><<<dim3(32, 4, BB), 256, SMEM_NN>>>(
        p_source, out_am, out_wc, IDF_, QQ, LL, sSL, (long long)LL * QQ, sIQ);
}